// round 8
// baseline (speedup 1.0000x reference)
#include <cuda_runtime.h>
#include <cuda_bf16.h>

// GAE backward affine suffix scan, fused prefix-length search with
// latency-hidden window resolution.
//
//   L     = prefix length of mask row (prefix mask);  valid[t] = t < L
//   nd    = 1 - done
//   delta = r + GAMMA * values[t+1]*valid[t+1] * nd - v
//   g[t]  = valid[t] ? (delta + GAMMA*LAMBDA*nd * g[t+1]) : 0
//   adv = g ; ret = valid ? g + v : 0
//
// Warp 0 probes mask at stride 64 (before streaming loads). Ballot gives a
// 64-element window [w0, w0+64) containing the boundary. Threads below the
// window are provably valid, above provably invalid. Only the 8 window
// threads read real mask words; the block scan runs with the window treated
// as IDENTITY while that load is in flight, then g is fixed up with the
// window's contribution gW via g_true = b_in + a_in * gW.

#define GAMMA  0.999f
#define LAMBDA 0.95f
#define GL     (GAMMA * LAMBDA)
#define S_LEN  2048
#define TPB    256
#define EPT    8           // TPB*EPT == S_LEN
#define NW     (TPB / 32)  // 8 warps

__global__ __launch_bounds__(TPB)
void gae_kernel(const float* __restrict__ rewards,
                const float* __restrict__ values,
                const int*   __restrict__ dones,
                const int*   __restrict__ mask,
                float* __restrict__ adv_out,
                float* __restrict__ ret_out)
{
    const int tid  = threadIdx.x;
    const unsigned lane = tid & 31u;
    const unsigned warp = tid >> 5;

    const long long rowbase = (long long)blockIdx.x * S_LEN;
    const long long base    = rowbase + tid * EPT;

    // Phase 1: warp 0 issues stride-64 mask probes FIRST.
    int p1 = 0;
    if (warp == 0) p1 = __ldg(mask + rowbase + lane * 64);

    // Phase 2: coalesced streaming vector loads (touch-once -> evict-first).
    const float4* rp = reinterpret_cast<const float4*>(rewards + base);
    const float4* vp = reinterpret_cast<const float4*>(values  + base);
    const int4*   dp = reinterpret_cast<const int4*>(dones + base);
    float4 r4a = __ldcs(rp);     float4 r4b = __ldcs(rp + 1);
    float4 v4a = __ldcs(vp);     float4 v4b = __ldcs(vp + 1);
    int4   d4a = __ldcs(dp);     int4   d4b = __ldcs(dp + 1);

    // Ballot -> window start w0 (L in (w0, w0+64]); w0 = -64 means L == 0.
    __shared__ int w0_sh;
    if (warp == 0) {
        unsigned b1 = __ballot_sync(0xffffffffu, p1 != 0);
        if (lane == 0) w0_sh = (b1 == 0u) ? -64 : (int)(__popc(b1) - 1) * 64;
    }

    __shared__ float nbr[TPB];
    nbr[tid] = v4a.x;
    __syncthreads();
    const int w0 = w0_sh;
    float v_next = (tid + 1 < TPB) ? nbr[tid + 1] : 0.f;

    const int t0 = tid * EPT;
    const bool isWin   = (t0 >= w0) && (t0 < w0 + 64);
    const bool isBelow = (t0 < w0);                 // t0,w0 8-aligned -> whole chunk valid
    // (else: above window -> fully invalid)

    // Window threads: issue their mask loads NOW; consumed after the block
    // scan so the latency overlaps it.
    int4 m4a = make_int4(0,0,0,0), m4b = make_int4(0,0,0,0);
    int  m8 = 0;
    if (isWin) {
        const int4* mp = reinterpret_cast<const int4*>(mask + base);
        m4a = __ldg(mp);
        m4b = __ldg(mp + 1);
        if (t0 + EPT < S_LEN) m8 = __ldg(mask + base + EPT);
    }

    float r[EPT]  = {r4a.x, r4a.y, r4a.z, r4a.w, r4b.x, r4b.y, r4b.z, r4b.w};
    float v[EPT]  = {v4a.x, v4a.y, v4a.z, v4a.w, v4b.x, v4b.y, v4b.z, v4b.w};
    float nd[EPT] = {1.f - (float)d4a.x, 1.f - (float)d4a.y,
                     1.f - (float)d4a.z, 1.f - (float)d4a.w,
                     1.f - (float)d4b.x, 1.f - (float)d4b.y,
                     1.f - (float)d4b.z, 1.f - (float)d4b.w};
    float nv[EPT] = {v[1], v[2], v[3], v[4], v[5], v[6], v[7], v_next};

    // Unmasked per-element transforms (valid for all below-window elements).
    float c[EPT], d[EPT];
#pragma unroll
    for (int j = 0; j < EPT; ++j) {
        float delta = fmaf(GAMMA * nd[j], nv[j], r[j]) - v[j];
        c[j] = GL * nd[j];
        d[j] = delta;
    }

    // Thread-local provisional fold: real for below, identity otherwise.
    float A = 1.f, Bc = 0.f;
    if (isBelow) {
#pragma unroll
        for (int j = EPT - 1; j >= 0; --j) {
            Bc = fmaf(c[j], Bc, d[j]);
            A  = c[j] * A;
        }
    }

    // Warp-level inclusive suffix scan (Kogge-Stone, pairs).
    float a = A, b = Bc;
#pragma unroll
    for (int off = 1; off < 32; off <<= 1) {
        float ra = __shfl_down_sync(0xffffffffu, a, off);
        float rb = __shfl_down_sync(0xffffffffu, b, off);
        if (lane + off < 32) {
            b = fmaf(a, rb, b);
            a = a * ra;
        }
    }
    float ea = __shfl_down_sync(0xffffffffu, a, 1);
    float eb = __shfl_down_sync(0xffffffffu, b, 1);
    if (lane == 31) { ea = 1.f; eb = 0.f; }

    // Cross-warp affine-pair carry.
    __shared__ float wa[NW], wb[NW], wca[NW], wcb[NW];
    __shared__ float gW_sh;
    if (lane == 0) { wa[warp] = a; wb[warp] = b; }
    if (tid == 0 && w0 < 0) gW_sh = 0.f;   // L == 0: no window thread writes
    __syncthreads();
    if (warp == 0 && lane < NW) {
        float aa = wa[lane], bb = wb[lane];
#pragma unroll
        for (int off = 1; off < NW; off <<= 1) {
            float ra = __shfl_down_sync(0x000000ffu, aa, off);
            float rb = __shfl_down_sync(0x000000ffu, bb, off);
            if (lane + off < NW) {
                bb = fmaf(aa, rb, bb);
                aa = aa * ra;
            }
        }
        float ca = __shfl_down_sync(0x000000ffu, aa, 1);
        float cb = __shfl_down_sync(0x000000ffu, bb, 1);
        if (lane == NW - 1) { ca = 1.f; cb = 0.f; }
        wca[lane] = ca; wcb[lane] = cb;
    }

    // Window threads: build REAL masked transforms + intra-window scan.
    float gwin_in = 0.f;
    int   mwk[EPT];
    if (isWin) {
        int mw[EPT + 1] = {m4a.x, m4a.y, m4a.z, m4a.w,
                           m4b.x, m4b.y, m4b.z, m4b.w, m8};
#pragma unroll
        for (int j = 0; j < EPT; ++j) {
            mwk[j] = mw[j];
            float mkf = (float)mw[j];
            float mnf = (float)mw[j + 1];
            float delta = fmaf(GAMMA * nd[j], nv[j] * mnf, r[j]) - v[j];
            c[j] = mkf * GL * nd[j];
            d[j] = mkf * delta;
        }
        float Aw = 1.f, Bw = 0.f;
#pragma unroll
        for (int j = EPT - 1; j >= 0; --j) {
            Bw = fmaf(c[j], Bw, d[j]);
            Aw = c[j] * Aw;
        }
        // 8-lane suffix scan among contiguous window lanes [s, s+8).
        const unsigned s  = (unsigned)((w0 / EPT) & 31);
        const unsigned wm = 0xFFu << s;
        float aw = Aw, bw = Bw;
#pragma unroll
        for (int off = 1; off < 8; off <<= 1) {
            float ra = __shfl_down_sync(wm, aw, off);
            float rb = __shfl_down_sync(wm, bw, off);
            if (lane + off < s + 8) {
                bw = fmaf(aw, rb, bw);
                aw = aw * ra;
            }
        }
        float ebw = __shfl_down_sync(wm, bw, 1);
        if (lane == s + 7) ebw = 0.f;
        gwin_in = ebw;                    // carry from right (above window = 0)
        if (lane == s) gW_sh = bw;        // g at w0 (full window fold on 0)
    }
    __syncthreads();

    const float gW = gW_sh;

    float adv[EPT], ret[EPT];
    if (isBelow) {
        float a_in = ea * wca[warp];
        float b_in = fmaf(ea, wcb[warp], eb);
        float g = fmaf(a_in, gW, b_in);
#pragma unroll
        for (int j = EPT - 1; j >= 0; --j) {
            g = fmaf(c[j], g, d[j]);
            adv[j] = g;
            ret[j] = g + v[j];            // all valid below window
        }
    } else if (isWin) {
        float g = gwin_in;
#pragma unroll
        for (int j = EPT - 1; j >= 0; --j) {
            g = fmaf(c[j], g, d[j]);      // 0 where invalid (c=d=0)
            adv[j] = g;
            ret[j] = mwk[j] ? (g + v[j]) : 0.f;
        }
    } else {
#pragma unroll
        for (int j = 0; j < EPT; ++j) { adv[j] = 0.f; ret[j] = 0.f; }
    }

    float4* ap = reinterpret_cast<float4*>(adv_out + base);
    float4* tp = reinterpret_cast<float4*>(ret_out + base);
    __stcs(ap,     make_float4(adv[0], adv[1], adv[2], adv[3]));
    __stcs(ap + 1, make_float4(adv[4], adv[5], adv[6], adv[7]));
    __stcs(tp,     make_float4(ret[0], ret[1], ret[2], ret[3]));
    __stcs(tp + 1, make_float4(ret[4], ret[5], ret[6], ret[7]));
}

extern "C" void kernel_launch(void* const* d_in, const int* in_sizes, int n_in,
                              void* d_out, int out_size)
{
    const float* rewards = (const float*)d_in[0];
    const float* values  = (const float*)d_in[1];
    const int*   dones   = (const int*)d_in[2];
    const int*   mask    = (const int*)d_in[3];

    const int total = in_sizes[0];            // B * S
    const int B     = total / S_LEN;

    float* adv_out = (float*)d_out;
    float* ret_out = (float*)d_out + (long long)B * S_LEN;

    gae_kernel<<<B, TPB>>>(rewards, values, dones, mask, adv_out, ret_out);
}

// round 9
// speedup vs baseline: 1.1366x; 1.1366x over previous
#include <cuda_runtime.h>
#include <cuda_bf16.h>

// GAE backward affine suffix scan. Inputs: rewards f32 [B,S], values f32 [B,S],
// dones i32 [B,S], mask i32 [B,S] (PREFIX mask 1...1 0...0 per row).
// Output: [advantages; returns], 2*B*S floats.
//
//   L     = prefix length;  valid[t] = t < L
//   nd    = 1 - done
//   delta = r + GAMMA * values[t+1]*valid[t+1] * nd - v
//   g[t]  = valid[t] ? (delta + GAMMA*LAMBDA*nd * g[t+1]) : 0
//   adv = g ; ret = valid ? g + v : 0
//
// Mask traffic (~64 MiB) is replaced by:
//  kernel 1 (w0_kernel): one warp per row, 32 probes at stride 64, single
//    ballot -> 64-aligned window base w0 with w0 < L <= w0+64. ONE load
//    round, no dependent chain.
//  kernel 2 (gae_kernel): R6-style streaming scan; only the 8 threads whose
//    chunks intersect [w0, w0+64) load their actual mask words (9 words,
//    one 256B line per CTA), issued in the front batch -> no dependent
//    rounds. Everyone else derives validity from w0 alone.

#define GAMMA  0.999f
#define LAMBDA 0.95f
#define GL     (GAMMA * LAMBDA)
#define S_LEN  2048
#define TPB    256
#define EPT    8           // TPB*EPT == S_LEN
#define NW     (TPB / 32)  // 8 warps
#define MAX_B  8192

__device__ int g_w0[MAX_B];

__global__ __launch_bounds__(256)
void w0_kernel(const int* __restrict__ mask, int B)
{
    const int gw   = (blockIdx.x * 256 + threadIdx.x) >> 5;   // warp id = row
    const int lane = threadIdx.x & 31;
    if (gw >= B) return;

    // mask[64*lane] = 1 iff 64*lane < L (prefix mask).
    int p = __ldg(mask + (long long)gw * S_LEN + lane * 64);
    unsigned b = __ballot_sync(0xffffffffu, p != 0);
    if (lane == 0)
        g_w0[gw] = (b == 0u) ? -64 : (int)(__popc(b) - 1) * 64;  // w0 < L <= w0+64
}

__global__ __launch_bounds__(TPB)
void gae_kernel(const float* __restrict__ rewards,
                const float* __restrict__ values,
                const int*   __restrict__ dones,
                const int*   __restrict__ mask,
                float* __restrict__ adv_out,
                float* __restrict__ ret_out)
{
    const int tid  = threadIdx.x;
    const unsigned lane = tid & 31u;
    const unsigned warp = tid >> 5;

    const long long base = (long long)blockIdx.x * S_LEN + tid * EPT;
    const int t0 = tid * EPT;

    // Scalar window base (written by kernel 1; L2-resident 32KB table).
    const int w0 = __ldg(&g_w0[blockIdx.x]);

    // Coalesced streaming vector loads (touch-once -> evict-first).
    const float4* rp = reinterpret_cast<const float4*>(rewards + base);
    const float4* vp = reinterpret_cast<const float4*>(values  + base);
    const int4*   dp = reinterpret_cast<const int4*>(dones + base);
    float4 r4a = __ldcs(rp);     float4 r4b = __ldcs(rp + 1);
    float4 v4a = __ldcs(vp);     float4 v4b = __ldcs(vp + 1);
    int4   d4a = __ldcs(dp);     int4   d4b = __ldcs(dp + 1);

    // Window threads load their 9 boundary mask words (front batch, overlaps
    // the streaming loads above).
    const bool isWin = (t0 >= w0) && (t0 < w0 + 64);
    int4 m4a = make_int4(0,0,0,0), m4b = make_int4(0,0,0,0);
    int  m8 = 0;
    if (isWin) {
        const int4* mp = reinterpret_cast<const int4*>(mask + base);
        m4a = __ldg(mp);
        m4b = __ldg(mp + 1);
        if (t0 + EPT < S_LEN) m8 = __ldg(mask + base + EPT);
    }

    // Neighbor (t+1) value exchange.
    __shared__ float nbr[TPB];
    nbr[tid] = v4a.x;
    __syncthreads();
    float v_next = (tid + 1 < TPB) ? nbr[tid + 1] : 0.f;

    // Per-element validity.
    float mk[EPT], mn[EPT];
    if (isWin) {
        int mw[EPT + 1] = {m4a.x, m4a.y, m4a.z, m4a.w,
                           m4b.x, m4b.y, m4b.z, m4b.w, m8};
#pragma unroll
        for (int j = 0; j < EPT; ++j) {
            mk[j] = (float)mw[j];
            mn[j] = (float)mw[j + 1];
        }
    } else {
        const float all = (t0 < w0) ? 1.f : 0.f;   // below window: w0 < L -> valid
#pragma unroll
        for (int j = 0; j < EPT; ++j) { mk[j] = all; mn[j] = all; }
        // Below-window j=7: t+1 = t0+8 <= w0 < L -> mn=1 correct.
    }

    float r[EPT]  = {r4a.x, r4a.y, r4a.z, r4a.w, r4b.x, r4b.y, r4b.z, r4b.w};
    float v[EPT]  = {v4a.x, v4a.y, v4a.z, v4a.w, v4b.x, v4b.y, v4b.z, v4b.w};
    float nd[EPT] = {1.f - (float)d4a.x, 1.f - (float)d4a.y,
                     1.f - (float)d4a.z, 1.f - (float)d4a.w,
                     1.f - (float)d4b.x, 1.f - (float)d4b.y,
                     1.f - (float)d4b.z, 1.f - (float)d4b.w};
    float nv[EPT] = {v[1], v[2], v[3], v[4], v[5], v[6], v[7], v_next};

    // Per-element affine transforms (c, d); invalid steps -> (0, 0).
    float c[EPT], d[EPT];
#pragma unroll
    for (int j = 0; j < EPT; ++j) {
        float nvj   = nv[j] * mn[j];
        float delta = fmaf(GAMMA * nd[j], nvj, r[j]) - v[j];
        c[j] = mk[j] * GL * nd[j];
        d[j] = mk[j] * delta;
    }

    // Thread-local composition over the 8 steps (reverse time order).
    float A = 1.f, Bc = 0.f;
#pragma unroll
    for (int j = EPT - 1; j >= 0; --j) {
        Bc = fmaf(c[j], Bc, d[j]);
        A  = c[j] * A;
    }

    // Warp-level inclusive suffix scan (Kogge-Stone, shfl_down).
    float a = A, b = Bc;
#pragma unroll
    for (int off = 1; off < 32; off <<= 1) {
        float ra = __shfl_down_sync(0xffffffffu, a, off);
        float rb = __shfl_down_sync(0xffffffffu, b, off);
        if (lane + off < 32) {
            b = fmaf(a, rb, b);
            a = a * ra;
        }
    }
    // Exclusive suffix within warp: E_i = inclusive(i+1); identity at lane 31.
    float ea = __shfl_down_sync(0xffffffffu, a, 1);
    float eb = __shfl_down_sync(0xffffffffu, b, 1);
    if (lane == 31) { ea = 1.f; eb = 0.f; }

    // Cross-warp scan over NW=8 warp aggregates.
    __shared__ float wa[NW];
    __shared__ float wb[NW];
    __shared__ float wcarry[NW];
    if (lane == 0) { wa[warp] = a; wb[warp] = b; }
    __syncthreads();
    if (warp == 0 && lane < NW) {
        float aa = wa[lane], bb = wb[lane];
#pragma unroll
        for (int off = 1; off < NW; off <<= 1) {
            float ra = __shfl_down_sync(0x000000ffu, aa, off);
            float rb = __shfl_down_sync(0x000000ffu, bb, off);
            if (lane + off < NW) {
                bb = fmaf(aa, rb, bb);
                aa = aa * ra;
            }
        }
        float carry = __shfl_down_sync(0x000000ffu, bb, 1);
        if (lane == NW - 1) carry = 0.f;
        wcarry[lane] = carry;
    }
    __syncthreads();

    // Carry entering this thread's chunk from the right, then final pass.
    float g = fmaf(ea, wcarry[warp], eb);

    float adv[EPT], ret[EPT];
#pragma unroll
    for (int j = EPT - 1; j >= 0; --j) {
        g = fmaf(c[j], g, d[j]);   // exactly 0 where invalid (c=d=0)
        adv[j] = g;
        ret[j] = (mk[j] != 0.f) ? (g + v[j]) : 0.f;
    }

    float4* ap = reinterpret_cast<float4*>(adv_out + base);
    float4* tp = reinterpret_cast<float4*>(ret_out + base);
    __stcs(ap,     make_float4(adv[0], adv[1], adv[2], adv[3]));
    __stcs(ap + 1, make_float4(adv[4], adv[5], adv[6], adv[7]));
    __stcs(tp,     make_float4(ret[0], ret[1], ret[2], ret[3]));
    __stcs(tp + 1, make_float4(ret[4], ret[5], ret[6], ret[7]));
}

extern "C" void kernel_launch(void* const* d_in, const int* in_sizes, int n_in,
                              void* d_out, int out_size)
{
    const float* rewards = (const float*)d_in[0];
    const float* values  = (const float*)d_in[1];
    const int*   dones   = (const int*)d_in[2];
    const int*   mask    = (const int*)d_in[3];

    const int total = in_sizes[0];            // B * S
    const int B     = total / S_LEN;

    float* adv_out = (float*)d_out;
    float* ret_out = (float*)d_out + (long long)B * S_LEN;

    // Kernel 1: per-row window base (one warp per row, one load round).
    const int lb = 256;
    const int lg = (B * 32 + lb - 1) / lb;
    w0_kernel<<<lg, lb>>>(mask, B);

    // Kernel 2: streaming GAE scan with in-line boundary resolution.
    gae_kernel<<<B, TPB>>>(rewards, values, dones, mask, adv_out, ret_out);
}